// round 8
// baseline (speedup 1.0000x reference)
#include <cuda_runtime.h>
#include <cuda_bf16.h>
#include <math.h>

// Shapes: B=32, H=8, J=8192, K=128
#define B_ 32
#define H_ 8
#define J_ 8192
#define K_ 128
#define EPSV 1e-6f

#define CTA_THREADS 128
#define ROWS 256            // j rows per CTA
#define NCHUNK 32           // j chunks per batch = J_/ROWS
#define KC 16               // k per k-chunk (= 64 bytes per row per stage)
#define NKC 8               // k chunks = K_/KC
#define PAD 20              // floats per staged row (16 data + 4 pad); conflict-free LDS.128
#define BUF_FLOATS (ROWS * PAD)   // 5120 floats per buffer (20 KB); 2 buffers = 40 KB

typedef unsigned long long ull;

// scratch: exp(sharp - chunk_max), 32*8*8192 f32 = 8 MB
__device__ float g_scratch[B_ * H_ * J_];
// per-(b,h,chunk) partials {max, sumexp}
__device__ float2 g_part[B_ * H_ * NCHUNK];
// per-(b,h,chunk) final softmax scale
__device__ float g_scale[B_ * H_ * NCHUNK];

#define FMA2(d, a, b, c) asm("fma.rn.f32x2 %0, %1, %2, %3;" : "=l"(d) : "l"(a), "l"(b), "l"(c))
#define PACK2(d, lo, hi) asm("mov.b64 %0, {%1, %2};" : "=l"(d) : "f"(lo), "f"(hi))
#define UNPACK2(lo, hi, s) asm("mov.b64 {%0, %1}, %2;" : "=f"(lo), "=f"(hi) : "l"(s))

__device__ __forceinline__ void cp_async16(void* smem_dst, const void* gsrc) {
    unsigned saddr = (unsigned)__cvta_generic_to_shared(smem_dst);
    asm volatile("cp.async.cg.shared.global [%0], [%1], 16;" :: "r"(saddr), "l"(gsrc));
}

__global__ void __launch_bounds__(CTA_THREADS, 3)
cw_main_kernel(const float* __restrict__ memory,
               const float* __restrict__ keys,
               const float* __restrict__ strengths,
               const float* __restrict__ mask)
{
    extern __shared__ float sdata[];   // 2 * BUF_FLOATS

    const int b = blockIdx.y;
    const int chunk = blockIdx.x;      // NCHUNK chunks of ROWS j
    const int tid = threadIdx.x;       // 128 threads
    const int lane = tid & 31;
    const int wid = tid >> 5;          // 4 warps

    __shared__ __align__(16) float2 s_c[K_ * H_];  // [k][h] = (w, q); w=m^2*key, q=m^2
    __shared__ float s_kn[H_];
    __shared__ float s_sps[H_];
    __shared__ float s_redA[4][8];
    __shared__ float s_redB[4][8];

    // ---- coefficient prep ----
    const float* mk = mask + b * (H_ * K_);
    const float* ky = keys + b * (H_ * K_);
    for (int i = tid; i < H_ * K_; i += CTA_THREADS) {
        int h = i >> 7;
        int k = i & 127;
        float m = mk[i];
        float kv = ky[i];
        float m2 = m * m;
        s_c[k * 8 + h] = make_float2(m2 * kv, m2);
    }
    // keys_norm: warp w handles heads w and w+4
    #pragma unroll
    for (int hh = 0; hh < 2; ++hh) {
        int h = wid + hh * 4;
        float s = 0.f;
        #pragma unroll
        for (int kk = 0; kk < 4; ++kk) {
            int k = lane + kk * 32;
            float v = mk[h * K_ + k] * ky[h * K_ + k];
            s += v * v;
        }
        #pragma unroll
        for (int o = 16; o; o >>= 1) s += __shfl_xor_sync(0xffffffffu, s, o);
        if (lane == 0) s_kn[h] = sqrtf(s);
    }
    if (tid < H_) {
        float x = strengths[b * H_ + tid];
        s_sps[tid] = (x > 20.f) ? x : log1pf(__expf(x));
    }

    // ---- stage helper ----
    const float* gbase = memory + ((size_t)b * J_ + (size_t)chunk * ROWS) * K_;
    // per stage: 256 rows x 16 floats = 1024 x 16B ops; 8 per thread
    #define STAGE(kc, buf)                                                        \
        {                                                                         \
            float* dbase = sdata + (buf) * BUF_FLOATS;                            \
            _Pragma("unroll")                                                     \
            for (int it = 0; it < 8; ++it) {                                      \
                int idx = it * CTA_THREADS + tid;                                 \
                int row = idx >> 2;                                               \
                int seg = idx & 3;                                                \
                cp_async16(dbase + row * PAD + seg * 4,                           \
                           gbase + (size_t)row * K_ + (kc) * KC + seg * 4);       \
            }                                                                     \
            asm volatile("cp.async.commit_group;");                               \
        }

    STAGE(0, 0);
    __syncthreads();   // coefficients ready

    const ulonglong2* c2 = (const ulonglong2*)s_c;  // [k*4 + hp] -> heads 2hp, 2hp+1

    ull acc[2][8];     // [row][head] packed (P, N)
    #pragma unroll
    for (int r = 0; r < 2; ++r)
        #pragma unroll
        for (int h = 0; h < 8; ++h) acc[r][h] = 0ull;

    const int i0 = tid * (PAD / 4);            // row tid       (float4 units)
    const int i1 = (tid + 128) * (PAD / 4);    // row tid+128

    #pragma unroll
    for (int kc = 0; kc < NKC; ++kc) {
        if (kc < NKC - 1) {
            STAGE(kc + 1, (kc + 1) & 1);
            asm volatile("cp.async.wait_group 1;");
        } else {
            asm volatile("cp.async.wait_group 0;");
        }
        __syncthreads();

        const float4* dp = (const float4*)(sdata + (kc & 1) * BUF_FLOATS);
        #pragma unroll
        for (int k4 = 0; k4 < 4; ++k4) {
            float4 d0 = dp[i0 + k4];
            float4 d1 = dp[i1 + k4];
            float m0a[4] = {d0.x, d0.y, d0.z, d0.w};
            float m1a[4] = {d1.x, d1.y, d1.z, d1.w};
            #pragma unroll
            for (int kk = 0; kk < 4; ++kk) {
                const int kg = kc * KC + k4 * 4 + kk;
                ulonglong2 cA = c2[kg * 4 + 0];   // heads 0,1
                ulonglong2 cB = c2[kg * 4 + 1];   // heads 2,3
                ulonglong2 cC = c2[kg * 4 + 2];   // heads 4,5
                ulonglong2 cD = c2[kg * 4 + 3];   // heads 6,7
                {
                    float m = m0a[kk];
                    float ms = m * m;
                    ull mv; PACK2(mv, m, ms);
                    FMA2(acc[0][0], cA.x, mv, acc[0][0]);
                    FMA2(acc[0][1], cA.y, mv, acc[0][1]);
                    FMA2(acc[0][2], cB.x, mv, acc[0][2]);
                    FMA2(acc[0][3], cB.y, mv, acc[0][3]);
                    FMA2(acc[0][4], cC.x, mv, acc[0][4]);
                    FMA2(acc[0][5], cC.y, mv, acc[0][5]);
                    FMA2(acc[0][6], cD.x, mv, acc[0][6]);
                    FMA2(acc[0][7], cD.y, mv, acc[0][7]);
                }
                {
                    float m = m1a[kk];
                    float ms = m * m;
                    ull mv; PACK2(mv, m, ms);
                    FMA2(acc[1][0], cA.x, mv, acc[1][0]);
                    FMA2(acc[1][1], cA.y, mv, acc[1][1]);
                    FMA2(acc[1][2], cB.x, mv, acc[1][2]);
                    FMA2(acc[1][3], cB.y, mv, acc[1][3]);
                    FMA2(acc[1][4], cC.x, mv, acc[1][4]);
                    FMA2(acc[1][5], cC.y, mv, acc[1][5]);
                    FMA2(acc[1][6], cD.x, mv, acc[1][6]);
                    FMA2(acc[1][7], cD.y, mv, acc[1][7]);
                }
            }
        }
        __syncthreads();   // all reads of this buffer done before restage
    }

    // ---- epilogue: sharp = P/(kn*sqrt(N)+eps) * sps ----
    float sharp[2][8];
    #pragma unroll
    for (int r = 0; r < 2; ++r) {
        #pragma unroll
        for (int h = 0; h < 8; ++h) {
            float P, N;
            UNPACK2(P, N, acc[r][h]);
            sharp[r][h] = P / (s_kn[h] * sqrtf(N) + EPSV) * s_sps[h];
        }
    }

    // ---- chunk-level softmax partials ----
    float cmax[8];
    #pragma unroll
    for (int h = 0; h < 8; ++h) {
        float t = fmaxf(sharp[0][h], sharp[1][h]);
        #pragma unroll
        for (int o = 16; o; o >>= 1) t = fmaxf(t, __shfl_xor_sync(0xffffffffu, t, o));
        if (lane == 0) s_redA[wid][h] = t;
    }
    __syncthreads();
    #pragma unroll
    for (int h = 0; h < 8; ++h)
        cmax[h] = fmaxf(fmaxf(s_redA[0][h], s_redA[1][h]),
                        fmaxf(s_redA[2][h], s_redA[3][h]));

    float e[2][8];
    float csum[8];
    #pragma unroll
    for (int h = 0; h < 8; ++h) {
        float t0 = __expf(sharp[0][h] - cmax[h]);
        float t1 = __expf(sharp[1][h] - cmax[h]);
        e[0][h] = t0; e[1][h] = t1;
        float t = t0 + t1;
        #pragma unroll
        for (int o = 16; o; o >>= 1) t += __shfl_xor_sync(0xffffffffu, t, o);
        if (lane == 0) s_redB[wid][h] = t;
    }
    __syncthreads();
    #pragma unroll
    for (int h = 0; h < 8; ++h)
        csum[h] = s_redB[0][h] + s_redB[1][h] + s_redB[2][h] + s_redB[3][h];

    if (tid == 0) {
        #pragma unroll
        for (int h = 0; h < 8; ++h)
            g_part[(b * H_ + h) * NCHUNK + chunk] = make_float2(cmax[h], csum[h]);
    }

    // ---- store exp values to scratch (coalesced STG.32, rows tid & tid+128) ----
    const int j0 = chunk * ROWS + tid;
    #pragma unroll
    for (int h = 0; h < 8; ++h) {
        float* dst = g_scratch + (size_t)(b * H_ + h) * J_ + j0;
        dst[0]   = e[0][h];
        dst[128] = e[1][h];
    }
}

// one warp per (b,h) row: combine 32 chunk partials into per-chunk scales
__global__ void __launch_bounds__(32)
cw_scales_kernel()
{
    const int x = blockIdx.x;          // b*H + h  (256 rows)
    const int c = threadIdx.x;         // 32 chunks

    float2 p = g_part[x * NCHUNK + c];
    float M = p.x;
    #pragma unroll
    for (int o = 16; o; o >>= 1) M = fmaxf(M, __shfl_xor_sync(0xffffffffu, M, o));
    float ex = __expf(p.x - M);
    float s = p.y * ex;
    #pragma unroll
    for (int o = 16; o; o >>= 1) s += __shfl_xor_sync(0xffffffffu, s, o);
    g_scale[x * NCHUNK + c] = ex / s;
}

// pure streaming rescale: 16 MB through, no smem, no shuffles
__global__ void __launch_bounds__(512)
cw_finalize_kernel(float* __restrict__ out)
{
    const int x = blockIdx.y;          // b*H + h  (256 rows)
    const int q = blockIdx.x;          // quarter of the row
    const int tid = threadIdx.x;       // 512 threads

    const int i = q * 512 + tid;       // float4 index in row (2048 total)
    const int c = i >> 6;              // 64 float4 per 256-float chunk
    const float sc = __ldg(g_scale + x * NCHUNK + c);

    const float4* src = (const float4*)(g_scratch + (size_t)x * J_);
    float4* dst = (float4*)(out + (size_t)x * J_);
    float4 v = src[i];
    dst[i] = make_float4(v.x * sc, v.y * sc, v.z * sc, v.w * sc);
}

extern "C" void kernel_launch(void* const* d_in, const int* in_sizes, int n_in,
                              void* d_out, int out_size)
{
    const float* memory    = (const float*)d_in[0];
    const float* keys      = (const float*)d_in[1];
    const float* strengths = (const float*)d_in[2];
    const float* mask      = (const float*)d_in[3];
    float* out = (float*)d_out;

    static bool attr_set = false;
    if (!attr_set) {
        cudaFuncSetAttribute(cw_main_kernel,
                             cudaFuncAttributeMaxDynamicSharedMemorySize,
                             2 * BUF_FLOATS * (int)sizeof(float));
        attr_set = true;
    }

    cw_main_kernel<<<dim3(NCHUNK, B_), CTA_THREADS,
                     2 * BUF_FLOATS * sizeof(float)>>>(memory, keys, strengths, mask);
    cw_scales_kernel<<<B_ * H_, 32>>>();
    cw_finalize_kernel<<<dim3(4, B_ * H_), 512>>>(out);
}

// round 9
// speedup vs baseline: 1.1901x; 1.1901x over previous
#include <cuda_runtime.h>
#include <cuda_bf16.h>
#include <math.h>

// Shapes: B=32, H=8, J=8192, K=128
#define B_ 32
#define H_ 8
#define J_ 8192
#define K_ 128
#define EPSV 1e-6f

#define CTA_THREADS 128
#define ROWS 256            // j rows per CTA
#define NCHUNK 32           // j chunks per batch = J_/ROWS
#define KC 16               // k per k-chunk (= 64 bytes per row per stage)
#define NKC 8               // k chunks = K_/KC
#define PAD 20              // floats per staged row (16 data + 4 pad); conflict-free LDS.128
#define BUF_FLOATS (ROWS * PAD)   // 5120 floats per buffer (20 KB); 2 buffers = 40 KB

typedef unsigned long long ull;

// scratch: exp(sharp - chunk_max), 32*8*8192 f32 = 8 MB
__device__ float g_scratch[B_ * H_ * J_];
// per-(b,h,chunk) partials {max, sumexp}
__device__ float2 g_part[B_ * H_ * NCHUNK];
// per-(b,h,chunk) final softmax scale
__device__ float g_scale[B_ * H_ * NCHUNK];

#define FMA2(d, a, b, c) asm("fma.rn.f32x2 %0, %1, %2, %3;" : "=l"(d) : "l"(a), "l"(b), "l"(c))
#define MUL2(d, a, b)    asm("mul.rn.f32x2 %0, %1, %2;"     : "=l"(d) : "l"(a), "l"(b))
#define PACK2(d, lo, hi) asm("mov.b64 %0, {%1, %2};" : "=l"(d) : "f"(lo), "f"(hi))
#define UNPACK2(lo, hi, s) asm("mov.b64 {%0, %1}, %2;" : "=f"(lo), "=f"(hi) : "l"(s))

__device__ __forceinline__ void cp_async16(void* smem_dst, const void* gsrc) {
    unsigned saddr = (unsigned)__cvta_generic_to_shared(smem_dst);
    asm volatile("cp.async.cg.shared.global [%0], [%1], 16;" :: "r"(saddr), "l"(gsrc));
}

__global__ void __launch_bounds__(CTA_THREADS, 4)
cw_main_kernel(const float* __restrict__ memory,
               const float* __restrict__ keys,
               const float* __restrict__ strengths,
               const float* __restrict__ mask)
{
    extern __shared__ float sdata[];   // 2 * BUF_FLOATS

    const int b = blockIdx.y;
    const int chunk = blockIdx.x;      // NCHUNK chunks of ROWS j
    const int tid = threadIdx.x;       // 128 threads
    const int lane = tid & 31;
    const int wid = tid >> 5;          // 4 warps

    __shared__ float s_w[K_ * H_];     // [k][h]
    __shared__ float s_m2[K_ * H_];    // [k][h]
    __shared__ float s_kn[H_];
    __shared__ float s_sps[H_];
    __shared__ float s_redA[4][8];
    __shared__ float s_redB[4][8];

    // ---- coefficient prep ----
    const float* mk = mask + b * (H_ * K_);
    const float* ky = keys + b * (H_ * K_);
    for (int i = tid; i < H_ * K_; i += CTA_THREADS) {
        int h = i >> 7;
        int k = i & 127;
        float m = mk[i];
        float kv = ky[i];
        float m2 = m * m;
        s_w[k * 8 + h]  = m2 * kv;
        s_m2[k * 8 + h] = m2;
    }
    // keys_norm: warp w handles heads w and w+4
    #pragma unroll
    for (int hh = 0; hh < 2; ++hh) {
        int h = wid + hh * 4;
        float s = 0.f;
        #pragma unroll
        for (int kk = 0; kk < 4; ++kk) {
            int k = lane + kk * 32;
            float v = mk[h * K_ + k] * ky[h * K_ + k];
            s += v * v;
        }
        #pragma unroll
        for (int o = 16; o; o >>= 1) s += __shfl_xor_sync(0xffffffffu, s, o);
        if (lane == 0) s_kn[h] = sqrtf(s);
    }
    if (tid < H_) {
        float x = strengths[b * H_ + tid];
        s_sps[tid] = (x > 20.f) ? x : log1pf(__expf(x));
    }

    // ---- stage helper ----
    const float* gbase = memory + ((size_t)b * J_ + (size_t)chunk * ROWS) * K_;
    // per stage: 256 rows x 16 floats = 1024 x 16B ops; 8 per thread
    #define STAGE(kc, buf)                                                        \
        {                                                                         \
            float* dbase = sdata + (buf) * BUF_FLOATS;                            \
            _Pragma("unroll")                                                     \
            for (int it = 0; it < 8; ++it) {                                      \
                int idx = it * CTA_THREADS + tid;                                 \
                int row = idx >> 2;                                               \
                int seg = idx & 3;                                                \
                cp_async16(dbase + row * PAD + seg * 4,                           \
                           gbase + (size_t)row * K_ + (kc) * KC + seg * 4);       \
            }                                                                     \
            asm volatile("cp.async.commit_group;");                               \
        }

    STAGE(0, 0);
    __syncthreads();   // coefficients ready

    const ull* w64 = (const ull*)s_w;
    const ull* q64 = (const ull*)s_m2;

    ull accP[2][4], accN[2][4];
    #pragma unroll
    for (int r = 0; r < 2; ++r)
        #pragma unroll
        for (int hp = 0; hp < 4; ++hp) { accP[r][hp] = 0ull; accN[r][hp] = 0ull; }

    const int i0 = tid * (PAD / 4);            // row tid       (float4 units)
    const int i1 = (tid + 128) * (PAD / 4);    // row tid+128

    #pragma unroll
    for (int kc = 0; kc < NKC; ++kc) {
        if (kc < NKC - 1) {
            STAGE(kc + 1, (kc + 1) & 1);
            asm volatile("cp.async.wait_group 1;");
        } else {
            asm volatile("cp.async.wait_group 0;");
        }
        __syncthreads();

        const float4* dp = (const float4*)(sdata + (kc & 1) * BUF_FLOATS);
        #pragma unroll
        for (int k4 = 0; k4 < 4; ++k4) {
            float4 d0 = dp[i0 + k4];
            float4 d1 = dp[i1 + k4];
            float m0a[4] = {d0.x, d0.y, d0.z, d0.w};
            float m1a[4] = {d1.x, d1.y, d1.z, d1.w};
            #pragma unroll
            for (int kk = 0; kk < 4; ++kk) {
                const int kg = kc * KC + k4 * 4 + kk;
                ull w0 = w64[kg * 4 + 0], w1 = w64[kg * 4 + 1];
                ull w2 = w64[kg * 4 + 2], w3 = w64[kg * 4 + 3];
                ull q0 = q64[kg * 4 + 0], q1 = q64[kg * 4 + 1];
                ull q2 = q64[kg * 4 + 2], q3 = q64[kg * 4 + 3];
                {
                    float m = m0a[kk];
                    ull mm; PACK2(mm, m, m);
                    ull ms; MUL2(ms, mm, mm);
                    FMA2(accP[0][0], w0, mm, accP[0][0]);
                    FMA2(accN[0][0], q0, ms, accN[0][0]);
                    FMA2(accP[0][1], w1, mm, accP[0][1]);
                    FMA2(accN[0][1], q1, ms, accN[0][1]);
                    FMA2(accP[0][2], w2, mm, accP[0][2]);
                    FMA2(accN[0][2], q2, ms, accN[0][2]);
                    FMA2(accP[0][3], w3, mm, accP[0][3]);
                    FMA2(accN[0][3], q3, ms, accN[0][3]);
                }
                {
                    float m = m1a[kk];
                    ull mm; PACK2(mm, m, m);
                    ull ms; MUL2(ms, mm, mm);
                    FMA2(accP[1][0], w0, mm, accP[1][0]);
                    FMA2(accN[1][0], q0, ms, accN[1][0]);
                    FMA2(accP[1][1], w1, mm, accP[1][1]);
                    FMA2(accN[1][1], q1, ms, accN[1][1]);
                    FMA2(accP[1][2], w2, mm, accP[1][2]);
                    FMA2(accN[1][2], q2, ms, accN[1][2]);
                    FMA2(accP[1][3], w3, mm, accP[1][3]);
                    FMA2(accN[1][3], q3, ms, accN[1][3]);
                }
            }
        }
        __syncthreads();   // all reads of this buffer done before restage
    }

    // ---- epilogue: sharp = proj/(kn*sqrt(nrm2)+eps) * sps ----
    float sharp[2][8];
    #pragma unroll
    for (int r = 0; r < 2; ++r) {
        #pragma unroll
        for (int hp = 0; hp < 4; ++hp) {
            float p0, p1, n0, n1;
            UNPACK2(p0, p1, accP[r][hp]);
            UNPACK2(n0, n1, accN[r][hp]);
            const int h0 = hp * 2, h1 = hp * 2 + 1;
            sharp[r][h0] = p0 / (s_kn[h0] * sqrtf(n0) + EPSV) * s_sps[h0];
            sharp[r][h1] = p1 / (s_kn[h1] * sqrtf(n1) + EPSV) * s_sps[h1];
        }
    }

    // ---- chunk-level softmax partials ----
    float cmax[8];
    #pragma unroll
    for (int h = 0; h < 8; ++h) {
        float t = fmaxf(sharp[0][h], sharp[1][h]);
        #pragma unroll
        for (int o = 16; o; o >>= 1) t = fmaxf(t, __shfl_xor_sync(0xffffffffu, t, o));
        if (lane == 0) s_redA[wid][h] = t;
    }
    __syncthreads();
    #pragma unroll
    for (int h = 0; h < 8; ++h)
        cmax[h] = fmaxf(fmaxf(s_redA[0][h], s_redA[1][h]),
                        fmaxf(s_redA[2][h], s_redA[3][h]));

    float e[2][8];
    float csum[8];
    #pragma unroll
    for (int h = 0; h < 8; ++h) {
        float t0 = __expf(sharp[0][h] - cmax[h]);
        float t1 = __expf(sharp[1][h] - cmax[h]);
        e[0][h] = t0; e[1][h] = t1;
        float t = t0 + t1;
        #pragma unroll
        for (int o = 16; o; o >>= 1) t += __shfl_xor_sync(0xffffffffu, t, o);
        if (lane == 0) s_redB[wid][h] = t;
    }
    __syncthreads();
    #pragma unroll
    for (int h = 0; h < 8; ++h)
        csum[h] = s_redB[0][h] + s_redB[1][h] + s_redB[2][h] + s_redB[3][h];

    if (tid == 0) {
        #pragma unroll
        for (int h = 0; h < 8; ++h)
            g_part[(b * H_ + h) * NCHUNK + chunk] = make_float2(cmax[h], csum[h]);
    }

    // ---- store exp values to scratch (coalesced STG.32, rows tid & tid+128) ----
    const int j0 = chunk * ROWS + tid;
    #pragma unroll
    for (int h = 0; h < 8; ++h) {
        float* dst = g_scratch + (size_t)(b * H_ + h) * J_ + j0;
        dst[0]   = e[0][h];
        dst[128] = e[1][h];
    }
}

// one warp per (b,h) row: combine 32 chunk partials into per-chunk scales
__global__ void __launch_bounds__(32)
cw_scales_kernel()
{
    const int x = blockIdx.x;          // b*H + h  (256 rows)
    const int c = threadIdx.x;         // 32 chunks

    float2 p = g_part[x * NCHUNK + c];
    float M = p.x;
    #pragma unroll
    for (int o = 16; o; o >>= 1) M = fmaxf(M, __shfl_xor_sync(0xffffffffu, M, o));
    float ex = __expf(p.x - M);
    float s = p.y * ex;
    #pragma unroll
    for (int o = 16; o; o >>= 1) s += __shfl_xor_sync(0xffffffffu, s, o);
    g_scale[x * NCHUNK + c] = ex / s;
}

// pure streaming rescale: 16 MB through, no smem, no shuffles
__global__ void __launch_bounds__(512)
cw_finalize_kernel(float* __restrict__ out)
{
    const int x = blockIdx.y;          // b*H + h  (256 rows)
    const int q = blockIdx.x;          // quarter of the row
    const int tid = threadIdx.x;       // 512 threads

    const int i = q * 512 + tid;       // float4 index in row (2048 total)
    const int c = i >> 6;              // 64 float4 per 256-float chunk
    const float sc = __ldg(g_scale + x * NCHUNK + c);

    const float4* src = (const float4*)(g_scratch + (size_t)x * J_);
    float4* dst = (float4*)(out + (size_t)x * J_);
    float4 v = src[i];
    dst[i] = make_float4(v.x * sc, v.y * sc, v.z * sc, v.w * sc);
}

extern "C" void kernel_launch(void* const* d_in, const int* in_sizes, int n_in,
                              void* d_out, int out_size)
{
    const float* memory    = (const float*)d_in[0];
    const float* keys      = (const float*)d_in[1];
    const float* strengths = (const float*)d_in[2];
    const float* mask      = (const float*)d_in[3];
    float* out = (float*)d_out;

    static bool attr_set = false;
    if (!attr_set) {
        cudaFuncSetAttribute(cw_main_kernel,
                             cudaFuncAttributeMaxDynamicSharedMemorySize,
                             2 * BUF_FLOATS * (int)sizeof(float));
        attr_set = true;
    }

    cw_main_kernel<<<dim3(NCHUNK, B_), CTA_THREADS,
                     2 * BUF_FLOATS * sizeof(float)>>>(memory, keys, strengths, mask);
    cw_scales_kernel<<<B_ * H_, 32>>>();
    cw_finalize_kernel<<<dim3(4, B_ * H_), 512>>>(out);
}